// round 17
// baseline (speedup 1.0000x reference)
#include <cuda_runtime.h>
#include <cuda_bf16.h>

// FrequencyAdaptiveNormSimple: out = sum_w softmax(alpha)[h,w] * (x - mu_w)/max(sd_w,1e-4)
// windows (5,10,20), replicate-padded stats for t < w-1. B=32,T=2048,H=512 fp32.
// 2 features/thread: LDG.64/STG.64, smem cumulative ring of ulonglong2
// (cs-pair, cq-pair -> LDS.128/STS.128), f32x2 packed maintenance math,
// scalar clamp/rsqrt/blend per lane. ~32% fewer issue slots per element.

typedef unsigned long long u64;

constexpr int Bc  = 32;
constexpr int Tc  = 2048;
constexpr int Hc  = 512;
constexpr int THR = 64;            // threads per block
constexpr int FPB = 2 * THR;       // features per block = 128
constexpr int TCc = 128;           // time chunk per block
constexpr int NCH = Tc / TCc;      // 16
constexpr int NHB = Hc / FPB;      // 4
constexpr int HS  = Hc / 2;        // u64 stride per timestep
static_assert(TCc % 20 == 8, "tail length assumed 8");

static __device__ __forceinline__ float rsq(float v) {
    float r; asm("rsqrt.approx.f32 %0, %1;" : "=f"(r) : "f"(v)); return r;
}
static __device__ __forceinline__ u64 f2add(u64 a, u64 b) {
    u64 d; asm("add.rn.f32x2 %0, %1, %2;" : "=l"(d) : "l"(a), "l"(b)); return d;
}
static __device__ __forceinline__ u64 f2mul(u64 a, u64 b) {
    u64 d; asm("mul.rn.f32x2 %0, %1, %2;" : "=l"(d) : "l"(a), "l"(b)); return d;
}
static __device__ __forceinline__ u64 f2fma(u64 a, u64 b, u64 c) {
    u64 d; asm("fma.rn.f32x2 %0, %1, %2, %3;" : "=l"(d) : "l"(a), "l"(b), "l"(c)); return d;
}
static __device__ __forceinline__ u64 f2pack(float lo, float hi) {
    u64 r; asm("mov.b64 %0, {%1, %2};" : "=l"(r) : "f"(lo), "f"(hi)); return r;
}
static __device__ __forceinline__ void f2unpack(u64 v, float& lo, float& hi) {
    asm("mov.b64 {%0, %1}, %2;" : "=f"(lo), "=f"(hi) : "l"(v));
}

// edge-path znorm (t < 20), plain scalar form
template <int W>
static __device__ __forceinline__ float zc(float xv, float s, float q, float al) {
    const float c1   = 1.0f / (float)(W - 1);
    const float c2   = 1.0f / ((float)W * (float)(W - 1));
    const float invW = 1.0f / (float)W;
    float var   = q * c1 - (s * c2) * s;
    float invsd = rsq(fmaxf(var, 1e-8f));
    return (xv - s * invW) * (al * invsd);
}

// one steady-state timestep for a feature PAIR; J literal so ring offsets are
// immediates. ring slot k holds packed cumulative (cs01, cq01) of time
// (tb-20+k) until step k overwrites it with time (tb+k).
#define STEP(J, V, OPTR) {                                            \
    u64 _v = (V);                                                     \
    ulonglong2 _g20 = ring[(J)][tid];          /* (t-20) */           \
    ulonglong2 _g10 = ring[((J) + 10) % 20][tid];                     \
    ulonglong2 _g5  = ring[((J) + 15) % 20][tid];                     \
    cs_run = f2add(cs_run, _v);                                       \
    cq_run = f2fma(_v, _v, cq_run);                                   \
    ring[(J)][tid] = make_ulonglong2(cs_run, cq_run);                 \
    u64 _s20 = f2fma(_g20.x, NEG1, cs_run);                           \
    u64 _q20 = f2fma(_g20.y, NEG1, cq_run);                           \
    u64 _s10 = f2fma(_g10.x, NEG1, cs_run);                           \
    u64 _q10 = f2fma(_g10.y, NEG1, cq_run);                           \
    u64 _s5  = f2fma(_g5.x,  NEG1, cs_run);                           \
    u64 _q5  = f2fma(_g5.y,  NEG1, cq_run);                           \
    u64 _t5  = f2mul(_s5,  NIW5);                                     \
    u64 _t10 = f2mul(_s10, NIW10);                                    \
    u64 _t20 = f2mul(_s20, NIW20);                                    \
    u64 _m5  = f2fma(_s5,  NIW5,  _v);                                \
    u64 _m10 = f2fma(_s10, NIW10, _v);                                \
    u64 _m20 = f2fma(_s20, NIW20, _v);                                \
    u64 _v5  = f2fma(_t5,  _s5,  _q5);                                \
    u64 _v10 = f2fma(_t10, _s10, _q10);                               \
    u64 _v20 = f2fma(_t20, _s20, _q20);                               \
    float _l, _h, _ml, _mh, _ol, _oh;                                 \
    f2unpack(_v5, _l, _h); f2unpack(_m5, _ml, _mh);                   \
    _ol = _ml * (a5l * rsq(fmaxf(_l, 4e-8f)));                        \
    _oh = _mh * (a5h * rsq(fmaxf(_h, 4e-8f)));                        \
    f2unpack(_v10, _l, _h); f2unpack(_m10, _ml, _mh);                 \
    _ol = fmaf(_ml, a10l * rsq(fmaxf(_l, 9e-8f)), _ol);               \
    _oh = fmaf(_mh, a10h * rsq(fmaxf(_h, 9e-8f)), _oh);               \
    f2unpack(_v20, _l, _h); f2unpack(_m20, _ml, _mh);                 \
    _ol = fmaf(_ml, a20l * rsq(fmaxf(_l, 19e-8f)), _ol);              \
    _oh = fmaf(_mh, a20h * rsq(fmaxf(_h, 19e-8f)), _oh);              \
    __stcs(&(OPTR)[(J) * HS], f2pack(_ol, _oh)); }

__global__ __launch_bounds__(THR)
void fan_kernel(const float* __restrict__ x,
                const float* __restrict__ alpha,
                float* __restrict__ out)
{
    __shared__ ulonglong2 ring[20][THR];   // packed cumulative ring, per-thread column

    const int tid   = threadIdx.x;
    int blk         = blockIdx.x;
    const int chunk = blk % NCH; blk /= NCH;
    const int hb    = blk % NHB; blk /= NHB;
    const int b     = blk;
    const int hbase = hb * FPB + 2 * tid;  // even -> 8B-aligned pair

    const float* xf = x   + (size_t)b * Tc * Hc + hbase;
    float*       of = out + (size_t)b * Tc * Hc + hbase;
    const u64*   xp = (const u64*)xf;      // stride HS per timestep
    u64*         op = (u64*)of;

    // ---- edge path first (chunk 0 only): t = 0..19, scalar per lane ----
    if (chunk == 0) {
        #pragma unroll 1
        for (int lane = 0; lane < 2; lane++) {
            const float* xe = xf + lane;
            float*       oe = of + lane;
            float w5, w10, w20;
            {
                float b0 = __ldg(&alpha[(hbase + lane) * 3 + 0]);
                float b1 = __ldg(&alpha[(hbase + lane) * 3 + 1]);
                float b2 = __ldg(&alpha[(hbase + lane) * 3 + 2]);
                float mx = fmaxf(b0, fmaxf(b1, b2));
                float e0 = __expf(b0 - mx), e1 = __expf(b1 - mx), e2 = __expf(b2 - mx);
                float ai = 1.0f / (e0 + e1 + e2);
                w5 = e0 * ai; w10 = e1 * ai; w20 = e2 * ai;
            }
            float r[20], ob[20];
            #pragma unroll
            for (int t = 0; t < 20; t++) { r[t] = __ldg(&xe[t * Hc]); ob[t] = 0.0f; }
            // w = 5
            {
                float s = 0.f, q = 0.f;
                #pragma unroll
                for (int t = 0; t < 20; t++) {
                    float v = r[t];
                    s += v; q += v * v;
                    if (t >= 5) { float l = r[t - 5]; s -= l; q -= l * l; }
                    if (t == 4) {
                        #pragma unroll
                        for (int tp = 0; tp <= 4; tp++) ob[tp] += zc<5>(r[tp], s, q, w5);
                    } else if (t > 4) {
                        ob[t] += zc<5>(v, s, q, w5);
                    }
                }
            }
            // w = 10
            {
                float s = 0.f, q = 0.f;
                #pragma unroll
                for (int t = 0; t < 20; t++) {
                    float v = r[t];
                    s += v; q += v * v;
                    if (t >= 10) { float l = r[t - 10]; s -= l; q -= l * l; }
                    if (t == 9) {
                        #pragma unroll
                        for (int tp = 0; tp <= 9; tp++) ob[tp] += zc<10>(r[tp], s, q, w10);
                    } else if (t > 9) {
                        ob[t] += zc<10>(v, s, q, w10);
                    }
                }
            }
            // w = 20
            {
                float s = 0.f, q = 0.f;
                #pragma unroll
                for (int t = 0; t < 20; t++) { float v = r[t]; s += v; q += v * v; }
                #pragma unroll
                for (int tp = 0; tp < 20; tp++) ob[tp] += zc<20>(r[tp], s, q, w20);
            }
            #pragma unroll
            for (int t = 0; t < 20; t++) __stcs(&oe[t * Hc], ob[t]);
        }
    }

    // ---- per-lane softmax, scaled for steady state (sqrt(W-1) folded) ----
    float a5l, a10l, a20l, a5h, a10h, a20h;
    {
        float b0 = __ldg(&alpha[hbase * 3 + 0]);
        float b1 = __ldg(&alpha[hbase * 3 + 1]);
        float b2 = __ldg(&alpha[hbase * 3 + 2]);
        float mx = fmaxf(b0, fmaxf(b1, b2));
        float e0 = __expf(b0 - mx), e1 = __expf(b1 - mx), e2 = __expf(b2 - mx);
        float ai = 1.0f / (e0 + e1 + e2);
        a5l = e0 * ai * 2.0f; a10l = e1 * ai * 3.0f; a20l = e2 * ai * 4.35889894354f;
        b0 = __ldg(&alpha[(hbase + 1) * 3 + 0]);
        b1 = __ldg(&alpha[(hbase + 1) * 3 + 1]);
        b2 = __ldg(&alpha[(hbase + 1) * 3 + 2]);
        mx = fmaxf(b0, fmaxf(b1, b2));
        e0 = __expf(b0 - mx); e1 = __expf(b1 - mx); e2 = __expf(b2 - mx);
        ai = 1.0f / (e0 + e1 + e2);
        a5h = e0 * ai * 2.0f; a10h = e1 * ai * 3.0f; a20h = e2 * ai * 4.35889894354f;
    }

    const u64 NEG1  = f2pack(-1.0f,  -1.0f);
    const u64 NIW5  = f2pack(-0.2f,  -0.2f);
    const u64 NIW10 = f2pack(-0.1f,  -0.1f);
    const u64 NIW20 = f2pack(-0.05f, -0.05f);

    // warmup source: 20 values ending at tbeg-1
    const int t0   = chunk * TCc;
    const int tbeg = (chunk == 0) ? 20 : t0;
    const u64* pw  = xp + (size_t)(tbeg - 20) * HS;

    u64 cs_run = 0ULL, cq_run = 0ULL;     // bit pattern of (0.f, 0.f)
    #pragma unroll
    for (int i = 0; i < 20; i++) {
        u64 v = __ldg(&pw[i * HS]);
        cs_run = f2add(cs_run, v);
        cq_run = f2fma(v, v, cq_run);
        ring[i][tid] = make_ulonglong2(cs_run, cq_run);
    }

    const int tend = t0 + TCc;
    int tb = tbeg;

    // ---- steady state: 20-step groups, 5-wide u64 load batches ----
    #pragma unroll 1
    for (; tb + 20 <= tend; tb += 20) {
        const u64* p = xp + (size_t)tb * HS;
        u64*       o = op + (size_t)tb * HS;
        u64 xv[5];
        #pragma unroll
        for (int j = 0; j < 5; j++) xv[j] = __ldg(&p[j * HS]);
        STEP(0, xv[0], o); STEP(1, xv[1], o); STEP(2, xv[2], o);
        STEP(3, xv[3], o); STEP(4, xv[4], o);
        #pragma unroll
        for (int j = 0; j < 5; j++) xv[j] = __ldg(&p[(j + 5) * HS]);
        STEP(5, xv[0], o); STEP(6, xv[1], o); STEP(7, xv[2], o);
        STEP(8, xv[3], o); STEP(9, xv[4], o);
        #pragma unroll
        for (int j = 0; j < 5; j++) xv[j] = __ldg(&p[(j + 10) * HS]);
        STEP(10, xv[0], o); STEP(11, xv[1], o); STEP(12, xv[2], o);
        STEP(13, xv[3], o); STEP(14, xv[4], o);
        #pragma unroll
        for (int j = 0; j < 5; j++) xv[j] = __ldg(&p[(j + 15) * HS]);
        STEP(15, xv[0], o); STEP(16, xv[1], o); STEP(17, xv[2], o);
        STEP(18, xv[3], o); STEP(19, xv[4], o);
    }

    // ---- fixed 8-step tail (ring phase is 0 mod 20 here) ----
    {
        const u64* p = xp + (size_t)tb * HS;
        u64*       o = op + (size_t)tb * HS;
        u64 xv[4];
        #pragma unroll
        for (int j = 0; j < 4; j++) xv[j] = __ldg(&p[j * HS]);
        STEP(0, xv[0], o); STEP(1, xv[1], o); STEP(2, xv[2], o); STEP(3, xv[3], o);
        #pragma unroll
        for (int j = 0; j < 4; j++) xv[j] = __ldg(&p[(j + 4) * HS]);
        STEP(4, xv[0], o); STEP(5, xv[1], o); STEP(6, xv[2], o); STEP(7, xv[3], o);
    }
}

extern "C" void kernel_launch(void* const* d_in, const int* in_sizes, int n_in,
                              void* d_out, int out_size) {
    const float* x     = (const float*)d_in[0];
    const float* alpha = (const float*)d_in[1];
    float*       out   = (float*)d_out;
    fan_kernel<<<dim3(Bc * NHB * NCH), dim3(THR)>>>(x, alpha, out);  // 2048 blocks
}